// round 16
// baseline (speedup 1.0000x reference)
#include <cuda_runtime.h>
#include <cuda_bf16.h>
#include <math.h>
#include <stdint.h>

// Problem constants
#define BQ 32
#define WQ 64
#define MQ 16
#define LQ 8192
#define NBQ 32
#define KSPL 16
#define PSL 64            // Fpart p-slots (l-tiles per batch)

// ---------------- scratch (device globals: allocation-free rule) ----------
__device__ __align__(16) uint32_t g_hpkA[BQ * WQ * LQ];   // packed bf16 hi|lo h (64 MB)
__device__ __align__(16) uint32_t g_hpkB[BQ * WQ * LQ];   // 64 MB
__device__ __align__(16) uint32_t g_Tpk[NBQ * LQ];        // packed basis [n][l] (1 MB)
__device__ __align__(16) uint32_t g_Bhi[NBQ * LQ];        // (T_hi,T_hi) pairs [n][l]
__device__ __align__(16) uint32_t g_Blo[NBQ * LQ];        // (T_lo,T_lo) pairs [n][l]
__device__ float    g_Fpart[BQ * NBQ * PSL * WQ];         // DFT partials [b][n][p][c] (16.8MB)
__device__ uint32_t g_coefpk[BQ * WQ * NBQ];              // packed coef (1 MB)
__device__ uint32_t g_convpk[4 * WQ * WQ];                // packed conv weights

__device__ __forceinline__ float gelu_exact(float v) {
    return 0.5f * v * (1.0f + erff(v * 0.70710678118654752440f));
}

// bf16 hi/lo packing: low 16 bits = hi part, high 16 bits = lo part
__device__ __forceinline__ uint32_t pk(float v) {
    __nv_bfloat16 h = __float2bfloat16(v);
    __nv_bfloat16 l = __float2bfloat16(v - __bfloat162float(h));
    return (uint32_t)__bfloat16_as_ushort(h) | ((uint32_t)__bfloat16_as_ushort(l) << 16);
}

// warp-level bf16 MMA (baseline PTX, sm_80+; tensor pipe)
__device__ __forceinline__ void mma16816(float* d, const uint32_t* a,
                                         uint32_t b0, uint32_t b1) {
    asm volatile(
        "mma.sync.aligned.m16n8k16.row.col.f32.bf16.bf16.f32 "
        "{%0,%1,%2,%3}, {%4,%5,%6,%7}, {%8,%9}, {%0,%1,%2,%3};"
        : "+f"(d[0]), "+f"(d[1]), "+f"(d[2]), "+f"(d[3])
        : "r"(a[0]), "r"(a[1]), "r"(a[2]), "r"(a[3]), "r"(b0), "r"(b1));
}

__device__ __forceinline__ void ldsm_x4(uint32_t* r, uint32_t addr) {
    asm volatile("ldmatrix.sync.aligned.m8n8.x4.shared.b16 {%0,%1,%2,%3}, [%4];"
                 : "=r"(r[0]), "=r"(r[1]), "=r"(r[2]), "=r"(r[3]) : "r"(addr));
}

// cp.async 16B (baseline PTX, sm_80+)
__device__ __forceinline__ void cp_async16(uint32_t saddr, const void* gptr) {
    asm volatile("cp.async.cg.shared.global [%0], [%1], 16;"
                 :: "r"(saddr), "l"(__cvta_generic_to_global(gptr)) : "memory");
}
#define CP_COMMIT()  asm volatile("cp.async.commit_group;" ::: "memory")
#define CP_WAIT1()   asm volatile("cp.async.wait_group 1;" ::: "memory")
#define CP_WAITALL() asm volatile("cp.async.wait_group 0;" ::: "memory")

// fused kernel smem layout (bytes). Row stride 400B: 16B-aligned and
// +4 banks/row -> LDSM conflict-free.
#define AS_B 400
#define OFF_A   0                     // A; post-mainloop: D fp32 [64][129]; then Fs [32][68]
#define OFF_BHI 51200
#define OFF_BLO 76800
#define GS_W 132                      // G/T row stride (words): 16B-aligned, +4 banks
#define OFF_G   36864                 // G u32 [64][132] = 33792 B (overlays B_hi tail)
#define OFF_T   70656                 // T u32 [2][32][132] = 33792 B (overlays B_lo tail)
#define FUSED_SMEM 104448

// fwd kernel smem (layer 0 only): 2 stages of {A[64][68w], Bh[32][68w], Bl[32][68w]}
#define FA_W 68
#define FSTAGE (128 * FA_W)
#define FWD_SMEM (2 * FSTAGE * 4)     // 69632 B

// ---------------------------------------------------------------------------
// Basis tables.
// ---------------------------------------------------------------------------
__global__ void build_table_kernel() {
    int idx = blockIdx.x * blockDim.x + threadIdx.x;  // 131072
    int k = idx >> 13;
    int l = idx & (LQ - 1);
    int m = (k * l) & (LQ - 1);
    float ang = (float)m * (6.283185307179586476925f / (float)LQ);
    float s, c;
    sincosf(ang, &s, &c);
    uint32_t cp = pk(c), sp = pk(s);
    g_Tpk[(2 * k) * LQ + l]     = cp;
    g_Tpk[(2 * k + 1) * LQ + l] = sp;
    uint32_t ch = cp & 0xFFFFu, cl = cp >> 16;
    uint32_t sh = sp & 0xFFFFu, sl = sp >> 16;
    g_Bhi[(2 * k) * LQ + l]     = ch | (ch << 16);
    g_Blo[(2 * k) * LQ + l]     = cl | (cl << 16);
    g_Bhi[(2 * k + 1) * LQ + l] = sh | (sh << 16);
    g_Blo[(2 * k + 1) * LQ + l] = sl | (sl << 16);
}

__global__ void convprep_kernel(const float* __restrict__ cw) {
    int idx = blockIdx.x * 256 + threadIdx.x;   // 16384
    g_convpk[idx] = pk(cw[idx]);
}

// ---------------------------------------------------------------------------
// Lifting -> packed h
// ---------------------------------------------------------------------------
__global__ void lift_kernel(const float* __restrict__ x,
                            const float* __restrict__ Pw,
                            const float* __restrict__ Pb,
                            uint32_t* __restrict__ hpk) {
    int idx = blockIdx.x * 256 + threadIdx.x;
    int l = idx & (LQ - 1);
    int w = (idx >> 13) & 63;
    int b = idx >> 19;
    float x0 = x[(b * 2 + 0) * LQ + l];
    float x1 = x[(b * 2 + 1) * LQ + l];
    hpk[idx] = pk(Pw[2 * w] * x0 + Pw[2 * w + 1] * x1 + Pb[w]);
}

// ---------------------------------------------------------------------------
// Forward DFT via cp.async + ldmatrix MMA (R13 — validated). LAYER 0 ONLY.
// Writes Fpart p-slots 0..15 (stride PSL).
// ---------------------------------------------------------------------------
__global__ void __launch_bounds__(256, 2) fwd_mma_kernel(const uint32_t* __restrict__ hpk) {
    extern __shared__ __align__(16) uint32_t sw[];
    int b = blockIdx.x;
    int ks = blockIdx.y;
    int t = threadIdx.x;
    int w = t >> 5;
    int lane = t & 31;
    int r = lane >> 2;
    int q = lane & 3;
    int g = lane >> 3;
    int rr = lane & 7;

    const uint32_t* hb = hpk + (size_t)b * 64 * LQ;
    const int base = ks * 512;
    uint32_t sbase = (uint32_t)__cvta_generic_to_shared(sw);

    uint32_t aBase = sbase + (uint32_t)((((g & 1) ? 8 : 0) + rr) * (FA_W * 4))
                   + ((g & 2) ? 16u : 0u) + (uint32_t)(w * 32);
    uint32_t bBase = sbase + (uint32_t)((64 + ((g & 2) ? 8 : 0) + rr) * (FA_W * 4))
                   + ((g & 1) ? 16u : 0u) + (uint32_t)(w * 32);

    float d[4][4][4];
#pragma unroll
    for (int mi = 0; mi < 4; mi++)
#pragma unroll
        for (int ni = 0; ni < 4; ni++)
#pragma unroll
            for (int e = 0; e < 4; e++) d[mi][ni][e] = 0.f;

    auto issue = [&](int chk, int st) {
        uint32_t sA = sbase + (uint32_t)(st * FSTAGE * 4);
        int lb = base + chk * 64;
#pragma unroll
        for (int j = 0; j < 4; j++) {
            int id = t + 256 * j;
            int c = id >> 4, col = (id & 15) * 4;
            cp_async16(sA + (uint32_t)((c * FA_W + col) * 4),
                       hb + (size_t)c * LQ + lb + col);
        }
#pragma unroll
        for (int j = 0; j < 4; j++) {
            int id = t + 256 * j;
            int half = id >> 9;
            int n = (id >> 4) & 31, col = (id & 15) * 4;
            const uint32_t* gt = (half ? g_Blo : g_Bhi) + (size_t)n * LQ + lb + col;
            cp_async16(sA + (uint32_t)(((64 + half * 32 + n) * FA_W + col) * 4), gt);
        }
    };

    issue(0, 0); CP_COMMIT();
    issue(1, 1); CP_COMMIT();

    for (int chk = 0; chk < 8; chk++) {
        CP_WAIT1();
        __syncthreads();
        uint32_t soff = (uint32_t)((chk & 1) * FSTAGE * 4);
        uint32_t a[4][4];
#pragma unroll
        for (int mi = 0; mi < 4; mi++)
            ldsm_x4(a[mi], aBase + soff + (uint32_t)(mi * 16 * FA_W * 4));
#pragma unroll
        for (int pass = 0; pass < 2; pass++) {
            uint32_t B0[4], B1[4];
            uint32_t bp = bBase + soff + (uint32_t)(pass * 32 * FA_W * 4);
            ldsm_x4(B0, bp);
            ldsm_x4(B1, bp + 16 * FA_W * 4);
#pragma unroll
            for (int mi = 0; mi < 4; mi++) {
                mma16816(d[mi][0], a[mi], B0[0], B0[1]);
                mma16816(d[mi][1], a[mi], B0[2], B0[3]);
                mma16816(d[mi][2], a[mi], B1[0], B1[1]);
                mma16816(d[mi][3], a[mi], B1[2], B1[3]);
            }
        }
        __syncthreads();
        if (chk + 2 < 8) issue(chk + 2, chk & 1);
        CP_COMMIT();
    }

    float* Dw = (float*)sw;
    float* dw = Dw + w * (32 * FA_W);
#pragma unroll
    for (int mi = 0; mi < 4; mi++)
#pragma unroll
        for (int ni = 0; ni < 4; ni++) {
            int c = mi * 16 + r;
            int n = ni * 8 + 2 * q;
            dw[n * FA_W + c]           = d[mi][ni][0];
            dw[(n + 1) * FA_W + c]     = d[mi][ni][1];
            dw[n * FA_W + c + 8]       = d[mi][ni][2];
            dw[(n + 1) * FA_W + c + 8] = d[mi][ni][3];
        }
    __syncthreads();

#pragma unroll
    for (int j = 0; j < 8; j++) {
        int idx = t + 256 * j;
        int n = idx >> 6;
        int c = idx & 63;
        float s = 0.f;
#pragma unroll
        for (int ww = 0; ww < 8; ww++)
            s += Dw[ww * (32 * FA_W) + n * FA_W + c];
        g_Fpart[((size_t)(b * NBQ + n) * PSL + ks) * 64 + c] = s;
    }
}

// ---------------------------------------------------------------------------
// Mode mixing -> packed coefficients; pcount = #valid Fpart p-slots.
// ---------------------------------------------------------------------------
__global__ void __launch_bounds__(256) mode_mix_kernel(const float* __restrict__ kwr,
                                                       const float* __restrict__ kwi,
                                                       int ib, int pcount) {
    int k = blockIdx.x;
    int bg = blockIdx.y;
    int t = threadIdx.x;
    int o = t & 63;
    int bb = t >> 6;
    int b = bg * 4 + bb;
    __shared__ float wrS[64 * 65], wiS[64 * 65];
    __shared__ float HrS[4][64], HsS[4][64];

    const float* wrG = kwr + ((size_t)ib * 16 + k) * 4096;
    const float* wiG = kwi + ((size_t)ib * 16 + k) * 4096;
#pragma unroll
    for (int j = 0; j < 16; j++) {
        int idx = t + 256 * j;
        int row = idx >> 6, col = idx & 63;
        wrS[row * 65 + col] = wrG[idx];
        wiS[row * 65 + col] = wiG[idx];
    }

    float hr = 0.f, hs = 0.f;
    const float* fr = g_Fpart + (size_t)(b * NBQ + 2 * k) * PSL * 64;
    const float* fs = g_Fpart + (size_t)(b * NBQ + 2 * k + 1) * PSL * 64;
#pragma unroll 16
    for (int p = 0; p < pcount; p++) {
        hr += fr[p * 64 + o];
        hs += fs[p * 64 + o];
    }
    HrS[bb][o] = hr;
    HsS[bb][o] = hs;
    __syncthreads();

    float ar = 0.f, ai = 0.f;
#pragma unroll 8
    for (int i = 0; i < 64; i++) {
        float xr = HrS[bb][i];
        float xi = -HsS[bb][i];
        float wrv = wrS[o * 65 + i];
        float wiv = wiS[o * 65 + i];
        ar += wrv * xr - wiv * xi;
        ai += wrv * xi + wiv * xr;
    }
    const float invL = 1.0f / (float)LQ;
    float cC, cS;
    if (k == 0) { cC = ar * invL;        cS = 0.f; }
    else        { cC = 2.f * ar * invL;  cS = -2.f * ai * invL; }
    g_coefpk[(b * 64 + o) * NBQ + 2 * k]     = pk(cC);
    g_coefpk[(b * 64 + o) * NBQ + 2 * k + 1] = pk(cS);
}

// ---------------------------------------------------------------------------
// Fused block via mma.sync bf16-split + ldmatrix (R12 — validated), PLUS
// (when !LAST) the forward DFT of the produced h tile as a side-GEMM:
//   Fpart[b][n][p=tile][o] = sum_l G[o,l] * T[l0+l, n]
// T slices cp.async-staged during the epilogue; G packed words staged to smem
// in the same loop that writes hout. Same bf16 hi/lo 2-pass scheme.
// ---------------------------------------------------------------------------
template <bool LAST>
__global__ void __launch_bounds__(256, 2) fused_mma_kernel(
    const uint32_t* __restrict__ hin, uint32_t* __restrict__ hout,
    const float* __restrict__ cb, int ib,
    const float* __restrict__ Qw, const float* __restrict__ Qb,
    float* __restrict__ outp) {
    extern __shared__ __align__(16) char smem[];
    char* Asm = smem + OFF_A;
    int b = blockIdx.y;
    int t = threadIdx.x;
    int wid = t >> 5;
    int lane = t & 31;
    int l0 = blockIdx.x * 128;

    const uint32_t* hsrc = hin + (size_t)b * 64 * LQ;
#pragma unroll
    for (int j = 0; j < 48; j++) {
        int id = t + 256 * j;            // 12288 = 96 ch x 128 l
        int c = id >> 7;
        int l = id & 127;
        const uint32_t* src = (c < 32) ? (g_Tpk + (size_t)c * LQ)
                                       : (hsrc + (size_t)(c - 32) * LQ);
        *(uint32_t*)(Asm + l * AS_B + c * 4) = src[l0 + l];
    }
#pragma unroll
    for (int j = 0; j < 24; j++) {
        int id = t + 256 * j;            // 6144 = 64 o x 96 c
        int o = id / 96;
        int c = id - o * 96;
        uint32_t u = (c < 32) ? g_coefpk[((size_t)b * 64 + o) * NBQ + c]
                              : g_convpk[ib * 4096 + o * 64 + (c - 32)];
        uint32_t wh = u & 0xFFFFu;
        uint32_t wl = u >> 16;
        *(uint32_t*)(smem + OFF_BHI + o * AS_B + c * 4) = wh | (wh << 16);
        *(uint32_t*)(smem + OFF_BLO + o * AS_B + c * 4) = wl | (wl << 16);
    }
    __syncthreads();

    int wm = wid >> 1;
    int wn = wid & 1;
    int r = lane >> 2;
    int q = lane & 3;
    int g = lane >> 3;
    int rr = lane & 7;
    uint32_t sbase = (uint32_t)__cvta_generic_to_shared(smem);
    uint32_t aAddr0 = sbase + OFF_A
                    + (uint32_t)((wm * 32 + ((g & 1) ? 8 : 0) + rr) * AS_B)
                    + ((g & 2) ? 16u : 0u);
    uint32_t aAddr1 = aAddr0 + 16 * AS_B;
    uint32_t bOff = (uint32_t)((wn * 32 + ((g & 2) ? 8 : 0) + rr) * AS_B)
                  + ((g & 1) ? 16u : 0u);
    uint32_t bAddrH0 = sbase + OFF_BHI + bOff;
    uint32_t bAddrH1 = bAddrH0 + 16 * AS_B;
    uint32_t bAddrL0 = sbase + OFF_BLO + bOff;
    uint32_t bAddrL1 = bAddrL0 + 16 * AS_B;

    float d[2][4][4];
#pragma unroll
    for (int mi = 0; mi < 2; mi++)
#pragma unroll
        for (int ni = 0; ni < 4; ni++)
#pragma unroll
            for (int e = 0; e < 4; e++) d[mi][ni][e] = 0.f;

#pragma unroll
    for (int ks = 0; ks < 12; ks++) {
        uint32_t kb = ks * 32;
        uint32_t a0[4], a1[4], B0[4], B1[4];
        ldsm_x4(a0, aAddr0 + kb);
        ldsm_x4(a1, aAddr1 + kb);
        ldsm_x4(B0, bAddrH0 + kb);
        ldsm_x4(B1, bAddrH1 + kb);
        mma16816(d[0][0], a0, B0[0], B0[1]);
        mma16816(d[0][1], a0, B0[2], B0[3]);
        mma16816(d[0][2], a0, B1[0], B1[1]);
        mma16816(d[0][3], a0, B1[2], B1[3]);
        mma16816(d[1][0], a1, B0[0], B0[1]);
        mma16816(d[1][1], a1, B0[2], B0[3]);
        mma16816(d[1][2], a1, B1[0], B1[1]);
        mma16816(d[1][3], a1, B1[2], B1[3]);
        ldsm_x4(B0, bAddrL0 + kb);
        ldsm_x4(B1, bAddrL1 + kb);
        mma16816(d[0][0], a0, B0[0], B0[1]);
        mma16816(d[0][1], a0, B0[2], B0[3]);
        mma16816(d[0][2], a0, B1[0], B1[1]);
        mma16816(d[0][3], a0, B1[2], B1[3]);
        mma16816(d[1][0], a1, B0[0], B0[1]);
        mma16816(d[1][1], a1, B0[2], B0[3]);
        mma16816(d[1][2], a1, B1[0], B1[1]);
        mma16816(d[1][3], a1, B1[2], B1[3]);
    }

    __syncthreads();                     // mainloop done; B regions go dead

    if (!LAST) {
        // stage T slices (2 x 32 n x 128 words) into OFF_T while epilogue runs
#pragma unroll
        for (int j = 0; j < 8; j++) {
            int id = t + 256 * j;        // 2048 x 16B
            int half = id >> 10;
            int n = (id >> 5) & 31;
            int colq = (id & 31) * 4;
            const uint32_t* gt = (half ? g_Blo : g_Bhi) + (size_t)n * LQ + l0 + colq;
            cp_async16(sbase + OFF_T + (uint32_t)(((half * 32 + n) * GS_W + colq) * 4), gt);
        }
        CP_COMMIT();
    }

    float* D = (float*)Asm;              // D[o][129]
#pragma unroll
    for (int mi = 0; mi < 2; mi++)
#pragma unroll
        for (int ni = 0; ni < 4; ni++) {
            int l = wm * 32 + mi * 16 + r;
            int o = wn * 32 + ni * 8 + q * 2;
            D[o * 129 + l]           = d[mi][ni][0];
            D[(o + 1) * 129 + l]     = d[mi][ni][1];
            D[o * 129 + l + 8]       = d[mi][ni][2];
            D[(o + 1) * 129 + l + 8] = d[mi][ni][3];
        }
    __syncthreads();

    if (!LAST) {
        uint32_t* G = (uint32_t*)(smem + OFF_G);   // [64 o][GS_W]
#pragma unroll
        for (int j = 0; j < 32; j++) {
            int idx = t + 256 * j;
            int o = idx >> 7;
            int l = idx & 127;
            float v = D[o * 129 + l] + __ldg(&cb[ib * 64 + o]);
            uint32_t gv = pk(gelu_exact(v));
            hout[((size_t)b * 64 + o) * LQ + l0 + l] = gv;
            G[o * GS_W + l] = gv;
        }
        CP_WAITALL();
        __syncthreads();

        // ---- side-GEMM: F[64 o, 32 n] = G x T, 2-pass hi/lo -------------
        int mi = wid >> 1;               // m16 tile (o)
        int nh = wid & 1;                // n16 half
        uint32_t gA = sbase + OFF_G
                    + (uint32_t)((mi * 16 + ((g & 1) ? 8 : 0) + rr) * (GS_W * 4))
                    + ((g & 2) ? 16u : 0u);
        uint32_t tB = sbase + OFF_T
                    + (uint32_t)((nh * 16 + ((g & 2) ? 8 : 0) + rr) * (GS_W * 4))
                    + ((g & 1) ? 16u : 0u);
        float f[2][4];
#pragma unroll
        for (int ni = 0; ni < 2; ni++)
#pragma unroll
            for (int e = 0; e < 4; e++) f[ni][e] = 0.f;

#pragma unroll
        for (int kk = 0; kk < 16; kk++) {
            uint32_t kb2 = kk * 32;
            uint32_t aG[4], Bt[4];
            ldsm_x4(aG, gA + kb2);
            ldsm_x4(Bt, tB + kb2);                          // pass hi
            mma16816(f[0], aG, Bt[0], Bt[1]);
            mma16816(f[1], aG, Bt[2], Bt[3]);
            ldsm_x4(Bt, tB + 32 * GS_W * 4 + kb2);          // pass lo
            mma16816(f[0], aG, Bt[0], Bt[1]);
            mma16816(f[1], aG, Bt[2], Bt[3]);
        }

        float* Fs = (float*)Asm;         // [32 n][68] (D region dead)
#pragma unroll
        for (int ni = 0; ni < 2; ni++) {
            int n = nh * 16 + ni * 8 + 2 * q;
            int o = mi * 16 + r;
            Fs[n * 68 + o]           = f[ni][0];
            Fs[(n + 1) * 68 + o]     = f[ni][1];
            Fs[n * 68 + o + 8]       = f[ni][2];
            Fs[(n + 1) * 68 + o + 8] = f[ni][3];
        }
        __syncthreads();

#pragma unroll
        for (int j = 0; j < 8; j++) {
            int idx = t + 256 * j;       // 2048 = 32 n x 64 o
            int n = idx >> 6;
            int o = idx & 63;
            g_Fpart[(((size_t)b * NBQ + n) * PSL + blockIdx.x) * 64 + o] = Fs[n * 68 + o];
        }
    } else {
        float* partS = (float*)(smem + OFF_BHI);
        int l = t & 127;
        int ob = t >> 7;
        float s = 0.f;
#pragma unroll
        for (int j = 0; j < 32; j++) {
            int o = ob + 2 * j;
            float v = D[o * 129 + l] + __ldg(&cb[ib * 64 + o]);
            s += __ldg(&Qw[o]) * gelu_exact(v);
        }
        partS[ob * 128 + l] = s;
        __syncthreads();
        if (t < 128)
            outp[(size_t)b * LQ + l0 + t] = partS[t] + partS[128 + t] + __ldg(&Qb[0]);
    }
}

// ---------------------------------------------------------------------------
extern "C" void kernel_launch(void* const* d_in, const int* in_sizes, int n_in,
                              void* d_out, int out_size) {
    const float* x   = (const float*)d_in[0];
    const float* Pw  = (const float*)d_in[1];
    const float* Pb  = (const float*)d_in[2];
    const float* kwr = (const float*)d_in[3];
    const float* kwi = (const float*)d_in[4];
    const float* cw  = (const float*)d_in[5];
    const float* cb  = (const float*)d_in[6];
    const float* Qw  = (const float*)d_in[7];
    const float* Qb  = (const float*)d_in[8];
    float* out = (float*)d_out;

    uint32_t *hA = nullptr, *hB = nullptr;
    cudaGetSymbolAddress((void**)&hA, g_hpkA);
    cudaGetSymbolAddress((void**)&hB, g_hpkB);

    cudaFuncSetAttribute(fused_mma_kernel<false>,
                         cudaFuncAttributeMaxDynamicSharedMemorySize, FUSED_SMEM);
    cudaFuncSetAttribute(fused_mma_kernel<true>,
                         cudaFuncAttributeMaxDynamicSharedMemorySize, FUSED_SMEM);
    cudaFuncSetAttribute(fwd_mma_kernel,
                         cudaFuncAttributeMaxDynamicSharedMemorySize, FWD_SMEM);

    build_table_kernel<<<(LQ * MQ) / 256, 256>>>();
    convprep_kernel<<<64, 256>>>(cw);
    lift_kernel<<<(BQ * WQ * LQ) / 256, 256>>>(x, Pw, Pb, hA);

    // layer-0 forward DFT (only standalone fwd pass; p-slots 0..15)
    fwd_mma_kernel<<<dim3(BQ, KSPL), 256, FWD_SMEM>>>(hA);

    uint32_t* cur = hA;
    uint32_t* nxt = hB;
    for (int ib = 0; ib < 4; ib++) {
        int pcount = (ib == 0) ? 16 : PSL;
        mode_mix_kernel<<<dim3(16, 8), 256>>>(kwr, kwi, ib, pcount);
        if (ib < 3) {
            fused_mma_kernel<false><<<dim3(LQ / 128, BQ), 256, FUSED_SMEM>>>(
                cur, nxt, cb, ib, Qw, Qb, out);
        } else {
            fused_mma_kernel<true><<<dim3(LQ / 128, BQ), 256, FUSED_SMEM>>>(
                cur, nxt, cb, ib, Qw, Qb, out);
        }
        uint32_t* tmp = cur; cur = nxt; nxt = tmp;
    }
}

// round 17
// speedup vs baseline: 1.0869x; 1.0869x over previous
#include <cuda_runtime.h>
#include <cuda_bf16.h>
#include <math.h>
#include <stdint.h>

// Problem constants
#define BQ 32
#define WQ 64
#define MQ 16
#define LQ 8192
#define NBQ 32
#define KSPL 16

// ---------------- scratch (device globals: allocation-free rule) ----------
__device__ __align__(16) uint32_t g_hpkA[BQ * WQ * LQ];   // packed bf16 hi|lo h (64 MB)
__device__ __align__(16) uint32_t g_hpkB[BQ * WQ * LQ];   // 64 MB
__device__ __align__(16) uint32_t g_Tpk[NBQ * LQ];        // packed basis [n][l] (1 MB)
__device__ __align__(16) uint32_t g_Bhi[NBQ * LQ];        // (T_hi,T_hi) pairs [n][l]
__device__ __align__(16) uint32_t g_Blo[NBQ * LQ];        // (T_lo,T_lo) pairs [n][l]
__device__ float    g_Fpart[BQ * NBQ * KSPL * WQ];        // DFT partials [b][n][p][c]
__device__ __align__(16) uint32_t g_coefhi[BQ * WQ * NBQ]; // (c_hi,c_hi) dup pairs
__device__ __align__(16) uint32_t g_coeflo[BQ * WQ * NBQ]; // (c_lo,c_lo) dup pairs
__device__ __align__(16) uint32_t g_convhi[4 * WQ * WQ];   // (w_hi,w_hi) dup pairs
__device__ __align__(16) uint32_t g_convlo[4 * WQ * WQ];   // (w_lo,w_lo) dup pairs

__device__ __forceinline__ float gelu_exact(float v) {
    return 0.5f * v * (1.0f + erff(v * 0.70710678118654752440f));
}

// bf16 hi/lo packing: low 16 bits = hi part, high 16 bits = lo part
__device__ __forceinline__ uint32_t pk(float v) {
    __nv_bfloat16 h = __float2bfloat16(v);
    __nv_bfloat16 l = __float2bfloat16(v - __bfloat162float(h));
    return (uint32_t)__bfloat16_as_ushort(h) | ((uint32_t)__bfloat16_as_ushort(l) << 16);
}

// warp-level bf16 MMA (baseline PTX, sm_80+; tensor pipe)
__device__ __forceinline__ void mma16816(float* d, const uint32_t* a,
                                         uint32_t b0, uint32_t b1) {
    asm volatile(
        "mma.sync.aligned.m16n8k16.row.col.f32.bf16.bf16.f32 "
        "{%0,%1,%2,%3}, {%4,%5,%6,%7}, {%8,%9}, {%0,%1,%2,%3};"
        : "+f"(d[0]), "+f"(d[1]), "+f"(d[2]), "+f"(d[3])
        : "r"(a[0]), "r"(a[1]), "r"(a[2]), "r"(a[3]), "r"(b0), "r"(b1));
}

__device__ __forceinline__ void ldsm_x4(uint32_t* r, uint32_t addr) {
    asm volatile("ldmatrix.sync.aligned.m8n8.x4.shared.b16 {%0,%1,%2,%3}, [%4];"
                 : "=r"(r[0]), "=r"(r[1]), "=r"(r[2]), "=r"(r[3]) : "r"(addr));
}

// cp.async 16B (baseline PTX, sm_80+)
__device__ __forceinline__ void cp_async16(uint32_t saddr, const void* gptr) {
    asm volatile("cp.async.cg.shared.global [%0], [%1], 16;"
                 :: "r"(saddr), "l"(__cvta_generic_to_global(gptr)) : "memory");
}
#define CP_COMMIT()  asm volatile("cp.async.commit_group;" ::: "memory")
#define CP_WAIT1()   asm volatile("cp.async.wait_group 1;" ::: "memory")
#define CP_WAITALL() asm volatile("cp.async.wait_group 0;" ::: "memory")

// fused kernel smem layout (bytes). Row stride 400B: 16B-aligned and
// +4 banks/row -> LDSM conflict-free.
#define AS_B 400
#define OFF_A   0                     // A; post-mainloop: D fp32 [64][129]
#define OFF_BHI 51200
#define OFF_BLO 76800
#define FUSED_SMEM 102400

// fwd kernel smem: 2 stages of {A[64][68w], Bh[32][68w], Bl[32][68w]}
#define FA_W 68
#define FSTAGE (128 * FA_W)
#define FWD_SMEM (2 * FSTAGE * 4)     // 69632 B

// ---------------------------------------------------------------------------
// Basis tables.
// ---------------------------------------------------------------------------
__global__ void build_table_kernel() {
    int idx = blockIdx.x * blockDim.x + threadIdx.x;  // 131072
    int k = idx >> 13;
    int l = idx & (LQ - 1);
    int m = (k * l) & (LQ - 1);
    float ang = (float)m * (6.283185307179586476925f / (float)LQ);
    float s, c;
    sincosf(ang, &s, &c);
    uint32_t cp = pk(c), sp = pk(s);
    g_Tpk[(2 * k) * LQ + l]     = cp;
    g_Tpk[(2 * k + 1) * LQ + l] = sp;
    uint32_t ch = cp & 0xFFFFu, cl = cp >> 16;
    uint32_t sh = sp & 0xFFFFu, sl = sp >> 16;
    g_Bhi[(2 * k) * LQ + l]     = ch | (ch << 16);
    g_Blo[(2 * k) * LQ + l]     = cl | (cl << 16);
    g_Bhi[(2 * k + 1) * LQ + l] = sh | (sh << 16);
    g_Blo[(2 * k + 1) * LQ + l] = sl | (sl << 16);
}

// conv weights -> duplicated hi/lo pair tables (pure-copy B staging)
__global__ void convprep_kernel(const float* __restrict__ cw) {
    int idx = blockIdx.x * 256 + threadIdx.x;   // 16384
    uint32_t u = pk(cw[idx]);
    uint32_t wh = u & 0xFFFFu;
    uint32_t wl = u >> 16;
    g_convhi[idx] = wh | (wh << 16);
    g_convlo[idx] = wl | (wl << 16);
}

// ---------------------------------------------------------------------------
// Lifting -> packed h
// ---------------------------------------------------------------------------
__global__ void lift_kernel(const float* __restrict__ x,
                            const float* __restrict__ Pw,
                            const float* __restrict__ Pb,
                            uint32_t* __restrict__ hpk) {
    int idx = blockIdx.x * 256 + threadIdx.x;
    int l = idx & (LQ - 1);
    int w = (idx >> 13) & 63;
    int b = idx >> 19;
    float x0 = x[(b * 2 + 0) * LQ + l];
    float x1 = x[(b * 2 + 1) * LQ + l];
    hpk[idx] = pk(Pw[2 * w] * x0 + Pw[2 * w + 1] * x1 + Pb[w]);
}

// ---------------------------------------------------------------------------
// Forward DFT via cp.async + ldmatrix MMA (R13 — validated).
// ---------------------------------------------------------------------------
__global__ void __launch_bounds__(256, 2) fwd_mma_kernel(const uint32_t* __restrict__ hpk) {
    extern __shared__ __align__(16) uint32_t sw[];
    int b = blockIdx.x;
    int ks = blockIdx.y;
    int t = threadIdx.x;
    int w = t >> 5;
    int lane = t & 31;
    int r = lane >> 2;
    int q = lane & 3;
    int g = lane >> 3;
    int rr = lane & 7;

    const uint32_t* hb = hpk + (size_t)b * 64 * LQ;
    const int base = ks * 512;
    uint32_t sbase = (uint32_t)__cvta_generic_to_shared(sw);

    uint32_t aBase = sbase + (uint32_t)((((g & 1) ? 8 : 0) + rr) * (FA_W * 4))
                   + ((g & 2) ? 16u : 0u) + (uint32_t)(w * 32);
    uint32_t bBase = sbase + (uint32_t)((64 + ((g & 2) ? 8 : 0) + rr) * (FA_W * 4))
                   + ((g & 1) ? 16u : 0u) + (uint32_t)(w * 32);

    float d[4][4][4];
#pragma unroll
    for (int mi = 0; mi < 4; mi++)
#pragma unroll
        for (int ni = 0; ni < 4; ni++)
#pragma unroll
            for (int e = 0; e < 4; e++) d[mi][ni][e] = 0.f;

    auto issue = [&](int chk, int st) {
        uint32_t sA = sbase + (uint32_t)(st * FSTAGE * 4);
        int lb = base + chk * 64;
#pragma unroll
        for (int j = 0; j < 4; j++) {
            int id = t + 256 * j;
            int c = id >> 4, col = (id & 15) * 4;
            cp_async16(sA + (uint32_t)((c * FA_W + col) * 4),
                       hb + (size_t)c * LQ + lb + col);
        }
#pragma unroll
        for (int j = 0; j < 4; j++) {
            int id = t + 256 * j;
            int half = id >> 9;
            int n = (id >> 4) & 31, col = (id & 15) * 4;
            const uint32_t* gt = (half ? g_Blo : g_Bhi) + (size_t)n * LQ + lb + col;
            cp_async16(sA + (uint32_t)(((64 + half * 32 + n) * FA_W + col) * 4), gt);
        }
    };

    issue(0, 0); CP_COMMIT();
    issue(1, 1); CP_COMMIT();

    for (int chk = 0; chk < 8; chk++) {
        CP_WAIT1();
        __syncthreads();
        uint32_t soff = (uint32_t)((chk & 1) * FSTAGE * 4);
        uint32_t a[4][4];
#pragma unroll
        for (int mi = 0; mi < 4; mi++)
            ldsm_x4(a[mi], aBase + soff + (uint32_t)(mi * 16 * FA_W * 4));
#pragma unroll
        for (int pass = 0; pass < 2; pass++) {
            uint32_t B0[4], B1[4];
            uint32_t bp = bBase + soff + (uint32_t)(pass * 32 * FA_W * 4);
            ldsm_x4(B0, bp);
            ldsm_x4(B1, bp + 16 * FA_W * 4);
#pragma unroll
            for (int mi = 0; mi < 4; mi++) {
                mma16816(d[mi][0], a[mi], B0[0], B0[1]);
                mma16816(d[mi][1], a[mi], B0[2], B0[3]);
                mma16816(d[mi][2], a[mi], B1[0], B1[1]);
                mma16816(d[mi][3], a[mi], B1[2], B1[3]);
            }
        }
        __syncthreads();
        if (chk + 2 < 8) issue(chk + 2, chk & 1);
        CP_COMMIT();
    }

    float* Dw = (float*)sw;
    float* dw = Dw + w * (32 * FA_W);
#pragma unroll
    for (int mi = 0; mi < 4; mi++)
#pragma unroll
        for (int ni = 0; ni < 4; ni++) {
            int c = mi * 16 + r;
            int n = ni * 8 + 2 * q;
            dw[n * FA_W + c]           = d[mi][ni][0];
            dw[(n + 1) * FA_W + c]     = d[mi][ni][1];
            dw[n * FA_W + c + 8]       = d[mi][ni][2];
            dw[(n + 1) * FA_W + c + 8] = d[mi][ni][3];
        }
    __syncthreads();

#pragma unroll
    for (int j = 0; j < 8; j++) {
        int idx = t + 256 * j;
        int n = idx >> 6;
        int c = idx & 63;
        float s = 0.f;
#pragma unroll
        for (int ww = 0; ww < 8; ww++)
            s += Dw[ww * (32 * FA_W) + n * FA_W + c];
        g_Fpart[((size_t)(b * NBQ + n) * KSPL + ks) * 64 + c] = s;
    }
}

// ---------------------------------------------------------------------------
// Mode mixing -> duplicated hi/lo coefficient tables.
// ---------------------------------------------------------------------------
__global__ void __launch_bounds__(256) mode_mix_kernel(const float* __restrict__ kwr,
                                                       const float* __restrict__ kwi, int ib) {
    int k = blockIdx.x;
    int bg = blockIdx.y;
    int t = threadIdx.x;
    int o = t & 63;
    int bb = t >> 6;
    int b = bg * 4 + bb;
    __shared__ float wrS[64 * 65], wiS[64 * 65];
    __shared__ float HrS[4][64], HsS[4][64];

    const float* wrG = kwr + ((size_t)ib * 16 + k) * 4096;
    const float* wiG = kwi + ((size_t)ib * 16 + k) * 4096;
#pragma unroll
    for (int j = 0; j < 16; j++) {
        int idx = t + 256 * j;
        int row = idx >> 6, col = idx & 63;
        wrS[row * 65 + col] = wrG[idx];
        wiS[row * 65 + col] = wiG[idx];
    }

    float hr = 0.f, hs = 0.f;
    const float* fr = g_Fpart + (size_t)(b * NBQ + 2 * k) * KSPL * 64;
    const float* fs = g_Fpart + (size_t)(b * NBQ + 2 * k + 1) * KSPL * 64;
#pragma unroll
    for (int p = 0; p < KSPL; p++) {
        hr += fr[p * 64 + o];
        hs += fs[p * 64 + o];
    }
    HrS[bb][o] = hr;
    HsS[bb][o] = hs;
    __syncthreads();

    float ar = 0.f, ai = 0.f;
#pragma unroll 8
    for (int i = 0; i < 64; i++) {
        float xr = HrS[bb][i];
        float xi = -HsS[bb][i];
        float wrv = wrS[o * 65 + i];
        float wiv = wiS[o * 65 + i];
        ar += wrv * xr - wiv * xi;
        ai += wrv * xi + wiv * xr;
    }
    const float invL = 1.0f / (float)LQ;
    float cC, cS;
    if (k == 0) { cC = ar * invL;        cS = 0.f; }
    else        { cC = 2.f * ar * invL;  cS = -2.f * ai * invL; }
    uint32_t uc = pk(cC), us = pk(cS);
    uint32_t uch = uc & 0xFFFFu, ucl = uc >> 16;
    uint32_t ush = us & 0xFFFFu, usl = us >> 16;
    size_t ix = (size_t)(b * 64 + o) * NBQ + 2 * k;
    g_coefhi[ix]     = uch | (uch << 16);
    g_coeflo[ix]     = ucl | (ucl << 16);
    g_coefhi[ix + 1] = ush | (ush << 16);
    g_coeflo[ix + 1] = usl | (usl << 16);
}

// ---------------------------------------------------------------------------
// Fused block via mma.sync bf16-split + ldmatrix (R12/13 — validated).
// B staging is now a pure cp.async copy from the precomputed dup tables,
// issued BEFORE the A-staging LDG/STS so it overlaps.
// ---------------------------------------------------------------------------
template <bool LAST>
__global__ void __launch_bounds__(256, 2) fused_mma_kernel(
    const uint32_t* __restrict__ hin, uint32_t* __restrict__ hout,
    const float* __restrict__ cb, int ib,
    const float* __restrict__ Qw, const float* __restrict__ Qb,
    float* __restrict__ outp) {
    extern __shared__ __align__(16) char smem[];
    char* Asm = smem + OFF_A;
    int b = blockIdx.y;
    int t = threadIdx.x;
    int wid = t >> 5;
    int lane = t & 31;
    int l0 = blockIdx.x * 128;
    uint32_t sbase = (uint32_t)__cvta_generic_to_shared(smem);

    // ---- B staging: pure cp.async copy (hi: j<6, lo: j>=6) --------------
    // 1536 chunks per half = 64 o-rows x 24 x 16B (8 coef + 16 conv).
#pragma unroll
    for (int j = 0; j < 12; j++) {
        int id = (j < 6) ? (t + 256 * j) : (t + 256 * (j - 6));
        int o = id / 24;
        int ch = id - o * 24;
        const uint32_t* src;
        if (j < 6)
            src = (ch < 8) ? (g_coefhi + (size_t)(b * 64 + o) * NBQ + ch * 4)
                           : (g_convhi + ib * 4096 + o * 64 + (ch - 8) * 4);
        else
            src = (ch < 8) ? (g_coeflo + (size_t)(b * 64 + o) * NBQ + ch * 4)
                           : (g_convlo + ib * 4096 + o * 64 + (ch - 8) * 4);
        uint32_t dst = sbase + (uint32_t)((j < 6 ? OFF_BHI : OFF_BLO) + o * AS_B + ch * 16);
        cp_async16(dst, src);
    }
    CP_COMMIT();

    // ---- A staging: 128 l x 96 ch (packed u32 = k-slot pairs) -----------
    const uint32_t* hsrc = hin + (size_t)b * 64 * LQ;
#pragma unroll
    for (int j = 0; j < 48; j++) {
        int id = t + 256 * j;            // 12288 = 96 ch x 128 l
        int c = id >> 7;
        int l = id & 127;
        const uint32_t* src = (c < 32) ? (g_Tpk + (size_t)c * LQ)
                                       : (hsrc + (size_t)(c - 32) * LQ);
        *(uint32_t*)(Asm + l * AS_B + c * 4) = src[l0 + l];
    }
    CP_WAITALL();
    __syncthreads();

    int wm = wid >> 1;
    int wn = wid & 1;
    int r = lane >> 2;
    int q = lane & 3;
    int g = lane >> 3;
    int rr = lane & 7;
    uint32_t aAddr0 = sbase + OFF_A
                    + (uint32_t)((wm * 32 + ((g & 1) ? 8 : 0) + rr) * AS_B)
                    + ((g & 2) ? 16u : 0u);
    uint32_t aAddr1 = aAddr0 + 16 * AS_B;
    uint32_t bOff = (uint32_t)((wn * 32 + ((g & 2) ? 8 : 0) + rr) * AS_B)
                  + ((g & 1) ? 16u : 0u);
    uint32_t bAddrH0 = sbase + OFF_BHI + bOff;
    uint32_t bAddrH1 = bAddrH0 + 16 * AS_B;
    uint32_t bAddrL0 = sbase + OFF_BLO + bOff;
    uint32_t bAddrL1 = bAddrL0 + 16 * AS_B;

    float d[2][4][4];
#pragma unroll
    for (int mi = 0; mi < 2; mi++)
#pragma unroll
        for (int ni = 0; ni < 4; ni++)
#pragma unroll
            for (int e = 0; e < 4; e++) d[mi][ni][e] = 0.f;

#pragma unroll
    for (int ks = 0; ks < 12; ks++) {
        uint32_t kb = ks * 32;
        uint32_t a0[4], a1[4], B0[4], B1[4];
        ldsm_x4(a0, aAddr0 + kb);
        ldsm_x4(a1, aAddr1 + kb);
        ldsm_x4(B0, bAddrH0 + kb);
        ldsm_x4(B1, bAddrH1 + kb);
        mma16816(d[0][0], a0, B0[0], B0[1]);
        mma16816(d[0][1], a0, B0[2], B0[3]);
        mma16816(d[0][2], a0, B1[0], B1[1]);
        mma16816(d[0][3], a0, B1[2], B1[3]);
        mma16816(d[1][0], a1, B0[0], B0[1]);
        mma16816(d[1][1], a1, B0[2], B0[3]);
        mma16816(d[1][2], a1, B1[0], B1[1]);
        mma16816(d[1][3], a1, B1[2], B1[3]);
        ldsm_x4(B0, bAddrL0 + kb);
        ldsm_x4(B1, bAddrL1 + kb);
        mma16816(d[0][0], a0, B0[0], B0[1]);
        mma16816(d[0][1], a0, B0[2], B0[3]);
        mma16816(d[0][2], a0, B1[0], B1[1]);
        mma16816(d[0][3], a0, B1[2], B1[3]);
        mma16816(d[1][0], a1, B0[0], B0[1]);
        mma16816(d[1][1], a1, B0[2], B0[3]);
        mma16816(d[1][2], a1, B1[0], B1[1]);
        mma16816(d[1][3], a1, B1[2], B1[3]);
    }

    __syncthreads();
    float* D = (float*)Asm;              // D[o][129]
#pragma unroll
    for (int mi = 0; mi < 2; mi++)
#pragma unroll
        for (int ni = 0; ni < 4; ni++) {
            int l = wm * 32 + mi * 16 + r;
            int o = wn * 32 + ni * 8 + q * 2;
            D[o * 129 + l]           = d[mi][ni][0];
            D[(o + 1) * 129 + l]     = d[mi][ni][1];
            D[o * 129 + l + 8]       = d[mi][ni][2];
            D[(o + 1) * 129 + l + 8] = d[mi][ni][3];
        }
    __syncthreads();

    if (!LAST) {
#pragma unroll
        for (int j = 0; j < 32; j++) {
            int idx = t + 256 * j;
            int o = idx >> 7;
            int l = idx & 127;
            float v = D[o * 129 + l] + __ldg(&cb[ib * 64 + o]);
            hout[((size_t)b * 64 + o) * LQ + l0 + l] = pk(gelu_exact(v));
        }
    } else {
        float* partS = (float*)(smem + OFF_BHI);
        int l = t & 127;
        int ob = t >> 7;
        float s = 0.f;
#pragma unroll
        for (int j = 0; j < 32; j++) {
            int o = ob + 2 * j;
            float v = D[o * 129 + l] + __ldg(&cb[ib * 64 + o]);
            s += __ldg(&Qw[o]) * gelu_exact(v);
        }
        partS[ob * 128 + l] = s;
        __syncthreads();
        if (t < 128)
            outp[(size_t)b * LQ + l0 + t] = partS[t] + partS[128 + t] + __ldg(&Qb[0]);
    }
}

// ---------------------------------------------------------------------------
extern "C" void kernel_launch(void* const* d_in, const int* in_sizes, int n_in,
                              void* d_out, int out_size) {
    const float* x   = (const float*)d_in[0];
    const float* Pw  = (const float*)d_in[1];
    const float* Pb  = (const float*)d_in[2];
    const float* kwr = (const float*)d_in[3];
    const float* kwi = (const float*)d_in[4];
    const float* cw  = (const float*)d_in[5];
    const float* cb  = (const float*)d_in[6];
    const float* Qw  = (const float*)d_in[7];
    const float* Qb  = (const float*)d_in[8];
    float* out = (float*)d_out;

    uint32_t *hA = nullptr, *hB = nullptr;
    cudaGetSymbolAddress((void**)&hA, g_hpkA);
    cudaGetSymbolAddress((void**)&hB, g_hpkB);

    cudaFuncSetAttribute(fused_mma_kernel<false>,
                         cudaFuncAttributeMaxDynamicSharedMemorySize, FUSED_SMEM);
    cudaFuncSetAttribute(fused_mma_kernel<true>,
                         cudaFuncAttributeMaxDynamicSharedMemorySize, FUSED_SMEM);
    cudaFuncSetAttribute(fwd_mma_kernel,
                         cudaFuncAttributeMaxDynamicSharedMemorySize, FWD_SMEM);

    build_table_kernel<<<(LQ * MQ) / 256, 256>>>();
    convprep_kernel<<<64, 256>>>(cw);
    lift_kernel<<<(BQ * WQ * LQ) / 256, 256>>>(x, Pw, Pb, hA);

    uint32_t* cur = hA;
    uint32_t* nxt = hB;
    for (int ib = 0; ib < 4; ib++) {
        fwd_mma_kernel<<<dim3(BQ, KSPL), 256, FWD_SMEM>>>(cur);
        mode_mix_kernel<<<dim3(16, 8), 256>>>(kwr, kwi, ib);
        if (ib < 3) {
            fused_mma_kernel<false><<<dim3(LQ / 128, BQ), 256, FUSED_SMEM>>>(
                cur, nxt, cb, ib, Qw, Qb, out);
        } else {
            fused_mma_kernel<true><<<dim3(LQ / 128, BQ), 256, FUSED_SMEM>>>(
                cur, nxt, cb, ib, Qw, Qb, out);
        }
        uint32_t* tmp = cur; cur = nxt; nxt = tmp;
    }
}